// round 9
// baseline (speedup 1.0000x reference)
#include <cuda_runtime.h>
#include <cuda_bf16.h>
#include <cstdint>

#define Bdim 64
#define Tdim 512
#define Idim 512
#define Hdim 1024
#define Gdim 4096
#define NCTA 128

typedef unsigned long long ull;

// ---------------- device globals (allocation-free scratch) ----------------------
__device__ float g_gates_x[(size_t)Tdim * Bdim * Gdim];          // [t][b][4096]
__device__ __nv_bfloat16 g_h[2][2][Bdim][Hdim];                  // [pp][hi/lo][b][k]
__device__ __nv_bfloat16 g_W_img[NCTA][2][32][Hdim];             // [jb][hi/lo][nl][k]
__device__ float g_c[NCTA][Bdim][8];                             // cell state

// ---------------- helpers --------------------------------------------------------
__device__ __forceinline__ uint32_t smem_u32(const void* p) {
    uint32_t a;
    asm("{ .reg .u64 t; cvta.to.shared.u64 t, %1; cvt.u32.u64 %0, t; }" : "=r"(a) : "l"(p));
    return a;
}
__device__ __forceinline__ void cp16(uint32_t dst, const void* src) {
    asm volatile("cp.async.ca.shared.global [%0], [%1], 16;" :: "r"(dst), "l"(src) : "memory");
}
__device__ __forceinline__ void cp_commit() {
    asm volatile("cp.async.commit_group;" ::: "memory");
}
template <int N>
__device__ __forceinline__ void cp_wait() {
    asm volatile("cp.async.wait_group %0;" :: "n"(N) : "memory");
}
__device__ __forceinline__ void barq(int id) {
    asm volatile("bar.sync %0, 256;" :: "r"(id) : "memory");
}
__device__ __forceinline__ void ldm_x4(uint32_t& r0, uint32_t& r1, uint32_t& r2,
                                       uint32_t& r3, uint32_t addr) {
    asm volatile("ldmatrix.sync.aligned.m8n8.x4.shared.b16 {%0,%1,%2,%3}, [%4];"
                 : "=r"(r0), "=r"(r1), "=r"(r2), "=r"(r3) : "r"(addr));
}
__device__ __forceinline__ void mma_bf16(float* c, uint32_t a0, uint32_t a1,
                                         uint32_t a2, uint32_t a3,
                                         uint32_t b0, uint32_t b1) {
    asm volatile(
        "mma.sync.aligned.m16n8k16.row.col.f32.bf16.bf16.f32 "
        "{%0,%1,%2,%3}, {%4,%5,%6,%7}, {%8,%9}, {%0,%1,%2,%3};"
        : "+f"(c[0]), "+f"(c[1]), "+f"(c[2]), "+f"(c[3])
        : "r"(a0), "r"(a1), "r"(a2), "r"(a3), "r"(b0), "r"(b1));
}
__device__ __forceinline__ ull pack2(float x, float y) {
    ull r; asm("mov.b64 %0, {%1,%2};" : "=l"(r) : "f"(x), "f"(y)); return r;
}
__device__ __forceinline__ void unpack2(ull v, float& x, float& y) {
    asm("mov.b64 {%0,%1}, %2;" : "=f"(x), "=f"(y) : "l"(v));
}
__device__ __forceinline__ void ffma2(ull& d, ull a, ull b) {
    asm("fma.rn.f32x2 %0, %1, %2, %0;" : "+l"(d) : "l"(a), "l"(b));
}
__device__ __forceinline__ float sigm_(float x) {
    return __fdividef(1.0f, 1.0f + __expf(-x));
}
__device__ __forceinline__ float tanh_(float x) {
    return 1.0f - __fdividef(2.0f, __expf(2.0f * x) + 1.0f);
}

// ---------------- init ------------------------------------------------------------
__global__ void init_state(float* __restrict__ out) {
    int i = blockIdx.x * blockDim.x + threadIdx.x;  // 65536 threads
    ((uint32_t*)g_h[0])[i] = 0u;
    ((float*)g_c)[i] = 0.0f;
    out[i] = 0.0f;
}

// ---------------- W_hh -> per-CTA bf16 hi/lo image ---------------------------------
__global__ __launch_bounds__(256) void w_prep(const float* __restrict__ Whh) {
    int bid = blockIdx.x;            // 4096 = 128 jb x 32 nl
    int jb = bid >> 5;
    int nl = bid & 31;
    int grow = (nl >> 3) * Hdim + jb * 8 + (nl & 7);
    const float* src = Whh + (size_t)grow * Hdim;
#pragma unroll
    for (int q = 0; q < 4; q++) {
        int k = q * 256 + threadIdx.x;
        float w = src[k];
        __nv_bfloat16 hi = __float2bfloat16(w);
        __nv_bfloat16 lo = __float2bfloat16(w - __bfloat162float(hi));
        g_W_img[jb][0][nl][k] = hi;
        g_W_img[jb][1][nl][k] = lo;
    }
}

// ---------------- GEMM1 (fp32x2 SIMT, proven) ---------------------------------------
__global__ __launch_bounds__(256) void gates_x_gemm(
    const float* __restrict__ seq, const float* __restrict__ Wih,
    const float* __restrict__ bih, const float* __restrict__ bhh) {
    __shared__ float As[8][132];
    __shared__ float Bs[8][132];

    const int tid = threadIdx.x;
    const int tx = tid & 15;
    const int ty = tid >> 4;
    const int m0 = blockIdx.y * 128;
    const int n0 = blockIdx.x * 128;

    const int lr = tid >> 1;
    const int lk = (tid & 1) * 4;
    const float* aptr = seq + (size_t)(m0 + lr) * Idim + lk;
    const float* bptr = Wih + (size_t)(n0 + lr) * Idim + lk;

    ull acc[8][4];
#pragma unroll
    for (int i = 0; i < 8; i++)
#pragma unroll
        for (int j = 0; j < 4; j++) acc[i][j] = 0ull;

    for (int k0 = 0; k0 < Idim; k0 += 8) {
        float4 av = *(const float4*)(aptr + k0);
        float4 bv = *(const float4*)(bptr + k0);
        As[lk + 0][lr] = av.x; As[lk + 1][lr] = av.y;
        As[lk + 2][lr] = av.z; As[lk + 3][lr] = av.w;
        Bs[lk + 0][lr] = bv.x; Bs[lk + 1][lr] = bv.y;
        Bs[lk + 2][lr] = bv.z; Bs[lk + 3][lr] = bv.w;
        __syncthreads();
#pragma unroll
        for (int k = 0; k < 8; k++) {
            float4 a0 = *(const float4*)&As[k][ty * 8];
            float4 a1 = *(const float4*)&As[k][ty * 8 + 4];
            ull pb0 = *(const ull*)&Bs[k][tx * 8 + 0];
            ull pb1 = *(const ull*)&Bs[k][tx * 8 + 2];
            ull pb2 = *(const ull*)&Bs[k][tx * 8 + 4];
            ull pb3 = *(const ull*)&Bs[k][tx * 8 + 6];
            float am[8] = {a0.x, a0.y, a0.z, a0.w, a1.x, a1.y, a1.z, a1.w};
#pragma unroll
            for (int i = 0; i < 8; i++) {
                ull pa = pack2(am[i], am[i]);
                ffma2(acc[i][0], pa, pb0);
                ffma2(acc[i][1], pa, pb1);
                ffma2(acc[i][2], pa, pb2);
                ffma2(acc[i][3], pa, pb3);
            }
        }
        __syncthreads();
    }

#pragma unroll
    for (int i = 0; i < 8; i++) {
        int m = m0 + ty * 8 + i;
        int b = m >> 9;        // T = 512
        int t = m & 511;
        float* orow = g_gates_x + (size_t)(t * Bdim + b) * Gdim;
#pragma unroll
        for (int j = 0; j < 4; j++) {
            int n = n0 + tx * 8 + j * 2;
            float x, y; unpack2(acc[i][j], x, y);
            orow[n]     = x + bih[n]     + bhh[n];
            orow[n + 1] = y + bih[n + 1] + bhh[n + 1];
        }
    }
}

// ---------------- per-step HMMA kernel (dual K pipelines, 16 warps) -----------------
// 128 CTAs x 512 thr. Quad q = w>>3 (256 threads) owns K-half [q*512, +512) with its
// own 2-stage cp.async ring + named barrier (1+q). Within a quad, warp wq = w&7:
// mt = wq&3 (batches mt*16..), nh = wq>>2 (gate cols nh*16..): m16 x n16 tile.
// Per k16-slice: 2 A-LDSM.x4 + 2 B-LDSM.x4, 6 MMAs (3 split terms x 2 n-tiles).
#define KC 128
#define SWZ(row, seg) ((unsigned)((row) * 256 + ((((seg) ^ ((row) & 7))) << 4)))
#define H_PL 16384               // 64 rows x 256
#define W_PL 8192                // 32 rows x 256
#define STG_BYTES (2 * H_PL + 2 * W_PL)   // 49152
#define OFF_WQ (2 * STG_BYTES)            // per-quad region = 2 stages
#define OFF_PRE (2 * OFF_WQ)              // 196608
#define PRE_SZ (64 * 36 * 4)              // 9216
#define SMEM_BYTES (OFF_PRE + 2 * PRE_SZ) // 215040

__global__ __launch_bounds__(512) void lstm_step_mma(
    const int* __restrict__ lens, float* __restrict__ out, int t) {
    extern __shared__ unsigned char smem[];
    const uint32_t sb = smem_u32(smem);
    float* pre0 = (float*)(smem + OFF_PRE);
    float* pre1 = (float*)(smem + OFF_PRE + PRE_SZ);

    const int tid = threadIdx.x;
    const int lane = tid & 31;
    const int w = tid >> 5;
    const int q = w >> 3;            // K-half
    const int wq = w & 7;
    const int mt = wq & 3;           // m-tile
    const int nh = wq >> 2;          // n-half
    const int tq = tid & 255;        // thread-in-quad
    const int jb = blockIdx.x;
    const int j0 = jb * 8;
    const int pp = t & 1;
    const uint32_t qbase = sb + q * OFF_WQ;
    const int barid = 1 + q;

    const __nv_bfloat16* hsrc = &g_h[pp][0][0][0];
    const __nv_bfloat16* wsrc = &g_W_img[jb][0][0][0];

    // ---- cp.async issuer: chunk kc (0..3) of this quad's K-half (256 thr, 12 ops)
    auto issue_chunk = [&](int kc) {
        uint32_t base = qbase + (kc & 1) * STG_BYTES;
        int koff = q * 512 + kc * KC;
#pragma unroll
        for (int r = 0; r < 8; r++) {         // h: 2048 ops / 256 thr
            int i = r * 256 + tq;
            int plane = i >> 10, rem = i & 1023;
            int row = rem >> 4, seg = rem & 15;
            const void* src = hsrc + ((size_t)plane * Bdim + row) * Hdim + koff + seg * 8;
            cp16(base + plane * H_PL + SWZ(row, seg), src);
        }
#pragma unroll
        for (int r = 0; r < 4; r++) {         // w: 1024 ops / 256 thr
            int i = r * 256 + tq;
            int plane = i >> 9, rem = i & 511;
            int row = rem >> 4, seg = rem & 15;
            const void* src = wsrc + ((size_t)plane * 32 + row) * Hdim + koff + seg * 8;
            cp16(base + 2 * H_PL + plane * W_PL + SWZ(row, seg), src);
        }
        cp_commit();
    };

    issue_chunk(0);

    // ---- tail-state prefetch (threads 0-63, b = tid)
    float gx[32], cst[8];
    int lb = 0;
    if (tid < 64) {
        const float* gxb = g_gates_x + ((size_t)t * Bdim + tid) * Gdim + j0;
#pragma unroll
        for (int g = 0; g < 4; g++) {
            float4 v0 = *(const float4*)(gxb + g * Hdim);
            float4 v1 = *(const float4*)(gxb + g * Hdim + 4);
            gx[g * 8 + 0] = v0.x; gx[g * 8 + 1] = v0.y; gx[g * 8 + 2] = v0.z; gx[g * 8 + 3] = v0.w;
            gx[g * 8 + 4] = v1.x; gx[g * 8 + 5] = v1.y; gx[g * 8 + 6] = v1.z; gx[g * 8 + 7] = v1.w;
        }
        float4 c0 = *(const float4*)&g_c[jb][tid][0];
        float4 c1 = *(const float4*)&g_c[jb][tid][4];
        cst[0] = c0.x; cst[1] = c0.y; cst[2] = c0.z; cst[3] = c0.w;
        cst[4] = c1.x; cst[5] = c1.y; cst[6] = c1.z; cst[7] = c1.w;
        lb = lens[tid];
    }

    // ---- per-lane fragment addressing (swizzled, proven in round 8)
    const int rowa = mt * 16 + (lane & 7) + ((lane >> 3) & 1) * 8;   // A row (batch)
    const int selA = (lane >> 4) & 1;
    const int xa = rowa & 7;
    const uint32_t a_base = (uint32_t)(rowa * 256);
    const int rowb = nh * 16 + (lane & 7) + ((lane >> 4) & 1) * 8;   // B row (gate col)
    const int selB = (lane >> 3) & 1;
    const int xb = rowb & 7;
    const uint32_t b_base = (uint32_t)(2 * H_PL + rowb * 256);

    float C0[2][4], C1[2][4], C2[2][4];
#pragma unroll
    for (int nt = 0; nt < 2; nt++)
#pragma unroll
        for (int k = 0; k < 4; k++) { C0[nt][k] = 0.f; C1[nt][k] = 0.f; C2[nt][k] = 0.f; }

    for (int kc = 0; kc < 4; kc++) {
        if (kc + 1 < 4) { issue_chunk(kc + 1); cp_wait<1>(); }
        else            { cp_wait<0>(); }
        barq(barid);                  // copies of chunk kc visible quad-wide

        uint32_t base = qbase + (kc & 1) * STG_BYTES;
#pragma unroll
        for (int ks = 0; ks < 8; ks++) {
            uint32_t aoff = base + a_base + (uint32_t)((((2 * ks + selA) ^ xa)) << 4);
            uint32_t boff = base + b_base + (uint32_t)((((2 * ks + selB) ^ xb)) << 4);
            uint32_t ah0, ah1, ah2, ah3, al0, al1, al2, al3;
            ldm_x4(ah0, ah1, ah2, ah3, aoff);
            ldm_x4(al0, al1, al2, al3, aoff + H_PL);
            uint32_t p0, p1, p2, p3;          // B hi: n-tiles (nh*16..+7, +8..+15)
            ldm_x4(p0, p1, p2, p3, boff);
            uint32_t s0, s1, s2, s3;          // B lo
            ldm_x4(s0, s1, s2, s3, boff + W_PL);

            mma_bf16(C0[0], ah0, ah1, ah2, ah3, p0, p1);
            mma_bf16(C0[1], ah0, ah1, ah2, ah3, p2, p3);
            mma_bf16(C1[0], ah0, ah1, ah2, ah3, s0, s1);
            mma_bf16(C1[1], ah0, ah1, ah2, ah3, s2, s3);
            mma_bf16(C2[0], al0, al1, al2, al3, p0, p1);
            mma_bf16(C2[1], al0, al1, al2, al3, p2, p3);
        }
        barq(barid);                  // all reads of buffer kc&1 done before next issue
    }

    // ---- stage per-quad partial sums -> pre_q[64][36]
    {
        float* preq = q ? pre1 : pre0;
        int g = lane >> 2, t2 = (lane & 3) * 2;
        int m = mt * 16 + g;
#pragma unroll
        for (int nt = 0; nt < 2; nt++) {
            float s0 = C0[nt][0] + C1[nt][0] + C2[nt][0];
            float s1 = C0[nt][1] + C1[nt][1] + C2[nt][1];
            float s2 = C0[nt][2] + C1[nt][2] + C2[nt][2];
            float s3 = C0[nt][3] + C1[nt][3] + C2[nt][3];
            int n = nh * 16 + nt * 8 + t2;
            *(float2*)&preq[m * 36 + n]       = make_float2(s0, s1);
            *(float2*)&preq[(m + 8) * 36 + n] = make_float2(s2, s3);
        }
    }
    __syncthreads();

    // ---- pointwise LSTM cell (threads 0-63, b = tid)
    if (tid < 64) {
        int b = tid;
        float hn[8];
        unsigned short hu[8], lu[8];
#pragma unroll
        for (int jj = 0; jj < 8; jj++) {
            float xi = pre0[b * 36 + jj]      + pre1[b * 36 + jj]      + gx[jj];
            float xf = pre0[b * 36 + 8 + jj]  + pre1[b * 36 + 8 + jj]  + gx[8 + jj];
            float xg = pre0[b * 36 + 16 + jj] + pre1[b * 36 + 16 + jj] + gx[16 + jj];
            float xo = pre0[b * 36 + 24 + jj] + pre1[b * 36 + 24 + jj] + gx[24 + jj];
            float i_ = sigm_(xi), f_ = sigm_(xf), g_ = tanh_(xg), o_ = sigm_(xo);
            float cn = f_ * cst[jj] + i_ * g_;
            cst[jj] = cn;
            float h = o_ * tanh_(cn);
            hn[jj] = h;
            __nv_bfloat16 hh = __float2bfloat16(h);
            __nv_bfloat16 hl = __float2bfloat16(h - __bfloat162float(hh));
            hu[jj] = __bfloat16_as_ushort(hh);
            lu[jj] = __bfloat16_as_ushort(hl);
        }
        *(float4*)&g_c[jb][b][0] = make_float4(cst[0], cst[1], cst[2], cst[3]);
        *(float4*)&g_c[jb][b][4] = make_float4(cst[4], cst[5], cst[6], cst[7]);

        uint4 vh, vl;
        vh.x = (uint32_t)hu[0] | ((uint32_t)hu[1] << 16);
        vh.y = (uint32_t)hu[2] | ((uint32_t)hu[3] << 16);
        vh.z = (uint32_t)hu[4] | ((uint32_t)hu[5] << 16);
        vh.w = (uint32_t)hu[6] | ((uint32_t)hu[7] << 16);
        vl.x = (uint32_t)lu[0] | ((uint32_t)lu[1] << 16);
        vl.y = (uint32_t)lu[2] | ((uint32_t)lu[3] << 16);
        vl.z = (uint32_t)lu[4] | ((uint32_t)lu[5] << 16);
        vl.w = (uint32_t)lu[6] | ((uint32_t)lu[7] << 16);
        int pp1 = pp ^ 1;
        *(uint4*)&g_h[pp1][0][b][j0] = vh;
        *(uint4*)&g_h[pp1][1][b][j0] = vl;

        if (lb > t) {
            float* ob = out + (size_t)b * Hdim + j0;
            *(float4*)(ob)     = make_float4(hn[0], hn[1], hn[2], hn[3]);
            *(float4*)(ob + 4) = make_float4(hn[4], hn[5], hn[6], hn[7]);
        }
    }
}

// ---------------- launch ------------------------------------------------------------
extern "C" void kernel_launch(void* const* d_in, const int* in_sizes, int n_in,
                              void* d_out, int out_size) {
    const float* seq   = (const float*)d_in[0];
    const int*   lensp = (const int*)d_in[1];
    const float* Wih   = (const float*)d_in[2];
    const float* Whh   = (const float*)d_in[3];
    const float* bih   = (const float*)d_in[4];
    const float* bhh   = (const float*)d_in[5];
    float* out = (float*)d_out;

    cudaFuncSetAttribute(lstm_step_mma,
                         cudaFuncAttributeMaxDynamicSharedMemorySize, SMEM_BYTES);

    init_state<<<256, 256>>>(out);
    w_prep<<<4096, 256>>>(Whh);

    dim3 g1(Gdim / 128, (Bdim * Tdim) / 128);
    gates_x_gemm<<<g1, 256>>>(seq, Wih, bih, bhh);

    for (int t = 0; t < Tdim; t++) {
        lstm_step_mma<<<NCTA, 512, SMEM_BYTES>>>(lensp, out, t);
    }
}

// round 10
// speedup vs baseline: 1.2084x; 1.2084x over previous
#include <cuda_runtime.h>
#include <cuda_bf16.h>
#include <cstdint>

#define Bdim 64
#define Tdim 512
#define Idim 512
#define Hdim 1024
#define Gdim 4096
#define NCTA 128

typedef unsigned long long ull;

// ---------------- device globals (allocation-free scratch) ----------------------
__device__ float g_gates_x[(size_t)Tdim * Bdim * Gdim];          // [t][b][4096]
// pre-swizzled chunk images: row*256B + ((seg ^ (row&7))<<4), 16 segs of 16B per row
__device__ __align__(16) unsigned char g_h_img[2][2][8][16384];  // [pp][plane][kc][64 rows]
__device__ __align__(16) unsigned char g_w_img[NCTA][2][8][8192]; // [jb][plane][kc][32 rows]
__device__ float g_c[NCTA][Bdim][8];                             // cell state

// ---------------- helpers --------------------------------------------------------
__device__ __forceinline__ uint32_t smem_u32(const void* p) {
    uint32_t a;
    asm("{ .reg .u64 t; cvta.to.shared.u64 t, %1; cvt.u32.u64 %0, t; }" : "=r"(a) : "l"(p));
    return a;
}
__device__ __forceinline__ void mbar_init(uint32_t a, uint32_t cnt) {
    asm volatile("mbarrier.init.shared.b64 [%0], %1;" :: "r"(a), "r"(cnt) : "memory");
}
__device__ __forceinline__ void mbar_expect(uint32_t a, uint32_t tx) {
    asm volatile("mbarrier.arrive.expect_tx.shared.b64 _, [%0], %1;" :: "r"(a), "r"(tx) : "memory");
}
__device__ __forceinline__ void mbar_wait(uint32_t a, uint32_t parity) {
    asm volatile(
        "{\n\t.reg .pred P;\n\t"
        "WL_%=:\n\t"
        "mbarrier.try_wait.parity.acquire.cta.shared::cta.b64 P, [%0], %1, 0x989680;\n\t"
        "@P bra WD_%=;\n\t"
        "bra WL_%=;\n\t"
        "WD_%=:\n\t}"
        :: "r"(a), "r"(parity) : "memory");
}
__device__ __forceinline__ void bulk_g2s(uint32_t dst, const void* src, uint32_t bytes,
                                         uint32_t mbar) {
    asm volatile(
        "cp.async.bulk.shared::cta.global.mbarrier::complete_tx::bytes [%0], [%1], %2, [%3];"
        :: "r"(dst), "l"(src), "r"(bytes), "r"(mbar) : "memory");
}
__device__ __forceinline__ void ldm_x4(uint32_t& r0, uint32_t& r1, uint32_t& r2,
                                       uint32_t& r3, uint32_t addr) {
    asm volatile("ldmatrix.sync.aligned.m8n8.x4.shared.b16 {%0,%1,%2,%3}, [%4];"
                 : "=r"(r0), "=r"(r1), "=r"(r2), "=r"(r3) : "r"(addr));
}
__device__ __forceinline__ void mma_bf16(float* c, uint32_t a0, uint32_t a1,
                                         uint32_t a2, uint32_t a3,
                                         uint32_t b0, uint32_t b1) {
    asm volatile(
        "mma.sync.aligned.m16n8k16.row.col.f32.bf16.bf16.f32 "
        "{%0,%1,%2,%3}, {%4,%5,%6,%7}, {%8,%9}, {%0,%1,%2,%3};"
        : "+f"(c[0]), "+f"(c[1]), "+f"(c[2]), "+f"(c[3])
        : "r"(a0), "r"(a1), "r"(a2), "r"(a3), "r"(b0), "r"(b1));
}
__device__ __forceinline__ ull pack2(float x, float y) {
    ull r; asm("mov.b64 %0, {%1,%2};" : "=l"(r) : "f"(x), "f"(y)); return r;
}
__device__ __forceinline__ void unpack2(ull v, float& x, float& y) {
    asm("mov.b64 {%0,%1}, %2;" : "=f"(x), "=f"(y) : "l"(v));
}
__device__ __forceinline__ void ffma2(ull& d, ull a, ull b) {
    asm("fma.rn.f32x2 %0, %1, %2, %0;" : "+l"(d) : "l"(a), "l"(b));
}
__device__ __forceinline__ float sigm_(float x) {
    return __fdividef(1.0f, 1.0f + __expf(-x));
}
__device__ __forceinline__ float tanh_(float x) {
    return 1.0f - __fdividef(2.0f, __expf(2.0f * x) + 1.0f);
}

// ---------------- init ------------------------------------------------------------
__global__ void init_state(float* __restrict__ out) {
    int i = blockIdx.x * blockDim.x + threadIdx.x;  // 65536 threads
    ((uint32_t*)g_h_img[0])[i] = 0u;   // zero pp=0 h image (256 KB)
    ((float*)g_c)[i] = 0.0f;
    out[i] = 0.0f;
}

// ---------------- W_hh -> pre-swizzled per-CTA chunk images -------------------------
__global__ __launch_bounds__(256) void w_prep(const float* __restrict__ Whh) {
    int bid = blockIdx.x;            // 4096 = 128 jb x 32 nl
    int jb = bid >> 5;
    int nl = bid & 31;
    int grow = (nl >> 3) * Hdim + jb * 8 + (nl & 7);
    const float* src = Whh + (size_t)grow * Hdim;
#pragma unroll
    for (int q = 0; q < 4; q++) {
        int k = q * 256 + threadIdx.x;
        float w = src[k];
        __nv_bfloat16 hi = __float2bfloat16(w);
        __nv_bfloat16 lo = __float2bfloat16(w - __bfloat162float(hi));
        int kc = k >> 7;
        int kk = k & 127;
        int seg = kk >> 3;
        uint32_t off = (uint32_t)(nl * 256 + ((seg ^ (nl & 7)) << 4) + (kk & 7) * 2);
        *(__nv_bfloat16*)(&g_w_img[jb][0][kc][off]) = hi;
        *(__nv_bfloat16*)(&g_w_img[jb][1][kc][off]) = lo;
    }
}

// ---------------- GEMM1 (fp32x2 SIMT, proven) ---------------------------------------
__global__ __launch_bounds__(256) void gates_x_gemm(
    const float* __restrict__ seq, const float* __restrict__ Wih,
    const float* __restrict__ bih, const float* __restrict__ bhh) {
    __shared__ float As[8][132];
    __shared__ float Bs[8][132];

    const int tid = threadIdx.x;
    const int tx = tid & 15;
    const int ty = tid >> 4;
    const int m0 = blockIdx.y * 128;
    const int n0 = blockIdx.x * 128;

    const int lr = tid >> 1;
    const int lk = (tid & 1) * 4;
    const float* aptr = seq + (size_t)(m0 + lr) * Idim + lk;
    const float* bptr = Wih + (size_t)(n0 + lr) * Idim + lk;

    ull acc[8][4];
#pragma unroll
    for (int i = 0; i < 8; i++)
#pragma unroll
        for (int j = 0; j < 4; j++) acc[i][j] = 0ull;

    for (int k0 = 0; k0 < Idim; k0 += 8) {
        float4 av = *(const float4*)(aptr + k0);
        float4 bv = *(const float4*)(bptr + k0);
        As[lk + 0][lr] = av.x; As[lk + 1][lr] = av.y;
        As[lk + 2][lr] = av.z; As[lk + 3][lr] = av.w;
        Bs[lk + 0][lr] = bv.x; Bs[lk + 1][lr] = bv.y;
        Bs[lk + 2][lr] = bv.z; Bs[lk + 3][lr] = bv.w;
        __syncthreads();
#pragma unroll
        for (int k = 0; k < 8; k++) {
            float4 a0 = *(const float4*)&As[k][ty * 8];
            float4 a1 = *(const float4*)&As[k][ty * 8 + 4];
            ull pb0 = *(const ull*)&Bs[k][tx * 8 + 0];
            ull pb1 = *(const ull*)&Bs[k][tx * 8 + 2];
            ull pb2 = *(const ull*)&Bs[k][tx * 8 + 4];
            ull pb3 = *(const ull*)&Bs[k][tx * 8 + 6];
            float am[8] = {a0.x, a0.y, a0.z, a0.w, a1.x, a1.y, a1.z, a1.w};
#pragma unroll
            for (int i = 0; i < 8; i++) {
                ull pa = pack2(am[i], am[i]);
                ffma2(acc[i][0], pa, pb0);
                ffma2(acc[i][1], pa, pb1);
                ffma2(acc[i][2], pa, pb2);
                ffma2(acc[i][3], pa, pb3);
            }
        }
        __syncthreads();
    }

#pragma unroll
    for (int i = 0; i < 8; i++) {
        int m = m0 + ty * 8 + i;
        int b = m >> 9;        // T = 512
        int t = m & 511;
        float* orow = g_gates_x + (size_t)(t * Bdim + b) * Gdim;
#pragma unroll
        for (int j = 0; j < 4; j++) {
            int n = n0 + tx * 8 + j * 2;
            float x, y; unpack2(acc[i][j], x, y);
            orow[n]     = x + bih[n]     + bhh[n];
            orow[n + 1] = y + bih[n + 1] + bhh[n + 1];
        }
    }
}

// ---------------- per-step HMMA kernel (bulk-DMA pipeline) ---------------------------
// 128 CTAs x 256 thr (8 warps). K in 8 chunks of 128; 4-stage smem ring, each stage
// filled by FOUR cp.async.bulk transfers (h hi/lo 16 KB, W hi/lo 8 KB) issued by
// thread 0, completing on the stage mbarrier. Warp w: mt=w&3 (batches mt*16..),
// nh=w>>2 (gate cols nh*16..): per k16 -> 2 A-LDSM.x4 + 2 B-LDSM.x4, 6 MMAs.
#define STG 49152                 // stage: Ahi 0 | Alo 16384 | Bhi 32768 | Blo 40960
#define OFF_PRE (4 * STG)         // 196608
#define OFF_MBAR (OFF_PRE + 64 * 36 * 4)          // 205824
#define SMEM_BYTES (OFF_MBAR + 64)                // 205888

__global__ __launch_bounds__(256) void lstm_step_mma(
    const int* __restrict__ lens, float* __restrict__ out, int t) {
    extern __shared__ unsigned char smem[];
    const uint32_t sb = smem_u32(smem);
    float* pre = (float*)(smem + OFF_PRE);        // [64][36]
    const uint32_t mb0 = sb + OFF_MBAR;           // 4 mbarriers, 8B apart

    const int tid = threadIdx.x;
    const int lane = tid & 31;
    const int w = tid >> 5;
    const int mt = w & 3;
    const int nh = w >> 2;
    const int jb = blockIdx.x;
    const int j0 = jb * 8;
    const int pp = t & 1;

    if (tid == 0) {
#pragma unroll
        for (int s = 0; s < 4; s++) mbar_init(mb0 + s * 8, 1);
    }
    __syncthreads();

    // bulk issuer for chunk kc -> stage kc&3
    auto issue_chunk = [&](int kc) {
        int s = kc & 3;
        uint32_t dst = sb + s * STG;
        uint32_t mb = mb0 + s * 8;
        mbar_expect(mb, 49152);
        bulk_g2s(dst,         &g_h_img[pp][0][kc][0], 16384, mb);
        bulk_g2s(dst + 16384, &g_h_img[pp][1][kc][0], 16384, mb);
        bulk_g2s(dst + 32768, &g_w_img[jb][0][kc][0],  8192, mb);
        bulk_g2s(dst + 40960, &g_w_img[jb][1][kc][0],  8192, mb);
    };

    if (tid == 0) { issue_chunk(0); issue_chunk(1); issue_chunk(2); }

    // ---- tail-state prefetch (threads 0-63, b = tid)
    float gx[32], cst[8];
    int lb = 0;
    if (tid < 64) {
        const float* gxb = g_gates_x + ((size_t)t * Bdim + tid) * Gdim + j0;
#pragma unroll
        for (int g = 0; g < 4; g++) {
            float4 v0 = *(const float4*)(gxb + g * Hdim);
            float4 v1 = *(const float4*)(gxb + g * Hdim + 4);
            gx[g * 8 + 0] = v0.x; gx[g * 8 + 1] = v0.y; gx[g * 8 + 2] = v0.z; gx[g * 8 + 3] = v0.w;
            gx[g * 8 + 4] = v1.x; gx[g * 8 + 5] = v1.y; gx[g * 8 + 6] = v1.z; gx[g * 8 + 7] = v1.w;
        }
        float4 c0 = *(const float4*)&g_c[jb][tid][0];
        float4 c1 = *(const float4*)&g_c[jb][tid][4];
        cst[0] = c0.x; cst[1] = c0.y; cst[2] = c0.z; cst[3] = c0.w;
        cst[4] = c1.x; cst[5] = c1.y; cst[6] = c1.z; cst[7] = c1.w;
        lb = lens[tid];
    }

    // ---- per-lane fragment addressing (swizzled; proven rounds 8-9)
    const int rowa = mt * 16 + (lane & 7) + ((lane >> 3) & 1) * 8;   // A row (batch)
    const int selA = (lane >> 4) & 1;
    const int xa = rowa & 7;
    const uint32_t a_base = (uint32_t)(rowa * 256);
    const int rowb = nh * 16 + (lane & 7) + ((lane >> 4) & 1) * 8;   // B row (gate col)
    const int selB = (lane >> 3) & 1;
    const int xb = rowb & 7;
    const uint32_t b_base = (uint32_t)(32768 + rowb * 256);

    float C0[2][4], C1[2][4], C2[2][4];
#pragma unroll
    for (int nt = 0; nt < 2; nt++)
#pragma unroll
        for (int k = 0; k < 4; k++) { C0[nt][k] = 0.f; C1[nt][k] = 0.f; C2[nt][k] = 0.f; }

    for (int kc = 0; kc < 8; kc++) {
        mbar_wait(mb0 + (kc & 3) * 8, (kc >> 2) & 1);

        uint32_t base = sb + (kc & 3) * STG;
#pragma unroll
        for (int ks = 0; ks < 8; ks++) {
            uint32_t aoff = base + a_base + (uint32_t)((((2 * ks + selA) ^ xa)) << 4);
            uint32_t boff = base + b_base + (uint32_t)((((2 * ks + selB) ^ xb)) << 4);
            uint32_t ah0, ah1, ah2, ah3, al0, al1, al2, al3;
            ldm_x4(ah0, ah1, ah2, ah3, aoff);
            ldm_x4(al0, al1, al2, al3, aoff + 16384);
            uint32_t p0, p1, p2, p3;          // B hi: n-tiles (nh*16..+7, +8..+15)
            ldm_x4(p0, p1, p2, p3, boff);
            uint32_t s0, s1, s2, s3;          // B lo
            ldm_x4(s0, s1, s2, s3, boff + 8192);

            mma_bf16(C0[0], ah0, ah1, ah2, ah3, p0, p1);
            mma_bf16(C0[1], ah0, ah1, ah2, ah3, p2, p3);
            mma_bf16(C1[0], ah0, ah1, ah2, ah3, s0, s1);
            mma_bf16(C1[1], ah0, ah1, ah2, ah3, s2, s3);
            mma_bf16(C2[0], al0, al1, al2, al3, p0, p1);
            mma_bf16(C2[1], al0, al1, al2, al3, p2, p3);
        }
        __syncthreads();                      // all reads of stage kc&3 retired
        if (tid == 0 && kc + 3 < 8) issue_chunk(kc + 3);
    }

    // ---- merge split terms -> pre[64][36]
    {
        int g = lane >> 2, t2 = (lane & 3) * 2;
        int m = mt * 16 + g;
#pragma unroll
        for (int nt = 0; nt < 2; nt++) {
            float s0 = C0[nt][0] + C1[nt][0] + C2[nt][0];
            float s1 = C0[nt][1] + C1[nt][1] + C2[nt][1];
            float s2 = C0[nt][2] + C1[nt][2] + C2[nt][2];
            float s3 = C0[nt][3] + C1[nt][3] + C2[nt][3];
            int n = nh * 16 + nt * 8 + t2;
            *(float2*)&pre[m * 36 + n]       = make_float2(s0, s1);
            *(float2*)&pre[(m + 8) * 36 + n] = make_float2(s2, s3);
        }
    }
    __syncthreads();

    // ---- pointwise LSTM cell (threads 0-63, b = tid)
    if (tid < 64) {
        int b = tid;
        float hn[8];
        unsigned short hu[8], lu[8];
#pragma unroll
        for (int jj = 0; jj < 8; jj++) {
            float xi = pre[b * 36 + jj]      + gx[jj];
            float xf = pre[b * 36 + 8 + jj]  + gx[8 + jj];
            float xg = pre[b * 36 + 16 + jj] + gx[16 + jj];
            float xo = pre[b * 36 + 24 + jj] + gx[24 + jj];
            float i_ = sigm_(xi), f_ = sigm_(xf), g_ = tanh_(xg), o_ = sigm_(xo);
            float cn = f_ * cst[jj] + i_ * g_;
            cst[jj] = cn;
            float h = o_ * tanh_(cn);
            hn[jj] = h;
            __nv_bfloat16 hh = __float2bfloat16(h);
            __nv_bfloat16 hl = __float2bfloat16(h - __bfloat162float(hh));
            hu[jj] = __bfloat16_as_ushort(hh);
            lu[jj] = __bfloat16_as_ushort(hl);
        }
        *(float4*)&g_c[jb][b][0] = make_float4(cst[0], cst[1], cst[2], cst[3]);
        *(float4*)&g_c[jb][b][4] = make_float4(cst[4], cst[5], cst[6], cst[7]);

        uint4 vh, vl;
        vh.x = (uint32_t)hu[0] | ((uint32_t)hu[1] << 16);
        vh.y = (uint32_t)hu[2] | ((uint32_t)hu[3] << 16);
        vh.z = (uint32_t)hu[4] | ((uint32_t)hu[5] << 16);
        vh.w = (uint32_t)hu[6] | ((uint32_t)hu[7] << 16);
        vl.x = (uint32_t)lu[0] | ((uint32_t)lu[1] << 16);
        vl.y = (uint32_t)lu[2] | ((uint32_t)lu[3] << 16);
        vl.z = (uint32_t)lu[4] | ((uint32_t)lu[5] << 16);
        vl.w = (uint32_t)lu[6] | ((uint32_t)lu[7] << 16);

        // h image write: chunk = j0>>7, seg = (j0&127)>>3, swizzled by batch row
        int pp1 = pp ^ 1;
        int jc = j0 >> 7;
        int sg = (j0 & 127) >> 3;
        uint32_t hoff = (uint32_t)(b * 256 + ((sg ^ (b & 7)) << 4));
        *(uint4*)(&g_h_img[pp1][0][jc][hoff]) = vh;
        *(uint4*)(&g_h_img[pp1][1][jc][hoff]) = vl;

        if (lb > t) {
            float* ob = out + (size_t)b * Hdim + j0;
            *(float4*)(ob)     = make_float4(hn[0], hn[1], hn[2], hn[3]);
            *(float4*)(ob + 4) = make_float4(hn[4], hn[5], hn[6], hn[7]);
        }
    }
}

// ---------------- launch ------------------------------------------------------------
extern "C" void kernel_launch(void* const* d_in, const int* in_sizes, int n_in,
                              void* d_out, int out_size) {
    const float* seq   = (const float*)d_in[0];
    const int*   lensp = (const int*)d_in[1];
    const float* Wih   = (const float*)d_in[2];
    const float* Whh   = (const float*)d_in[3];
    const float* bih   = (const float*)d_in[4];
    const float* bhh   = (const float*)d_in[5];
    float* out = (float*)d_out;

    cudaFuncSetAttribute(lstm_step_mma,
                         cudaFuncAttributeMaxDynamicSharedMemorySize, SMEM_BYTES);

    init_state<<<256, 256>>>(out);
    w_prep<<<4096, 256>>>(Whh);

    dim3 g1(Gdim / 128, (Bdim * Tdim) / 128);
    gates_x_gemm<<<g1, 256>>>(seq, Wih, bih, bhh);

    for (int t = 0; t < Tdim; t++) {
        lstm_step_mma<<<NCTA, 256, SMEM_BYTES>>>(lensp, out, t);
    }
}

// round 11
// speedup vs baseline: 1.2437x; 1.0293x over previous
#include <cuda_runtime.h>
#include <cuda_bf16.h>
#include <cstdint>

#define Bdim 64
#define Tdim 512
#define Idim 512
#define Hdim 1024
#define Gdim 4096
#define NCTA 128

typedef unsigned long long ull;

// ---------------- device globals (allocation-free scratch) ----------------------
__device__ float g_gates_x[(size_t)Tdim * Bdim * Gdim];          // [t][b][4096]
// pre-swizzled chunk images: row*256B + ((seg ^ (row&7))<<4)
__device__ __align__(16) unsigned char g_h_img[2][2][8][16384];  // [pp][plane][kc][64 rows]
__device__ __align__(16) unsigned char g_w_img[NCTA][2][8][8192]; // [jb][plane][kc][32 rows]
__device__ unsigned g_bar_cnt;

// ---------------- helpers --------------------------------------------------------
__device__ __forceinline__ uint32_t smem_u32(const void* p) {
    uint32_t a;
    asm("{ .reg .u64 t; cvta.to.shared.u64 t, %1; cvt.u32.u64 %0, t; }" : "=r"(a) : "l"(p));
    return a;
}
__device__ __forceinline__ void mbar_init(uint32_t a, uint32_t cnt) {
    asm volatile("mbarrier.init.shared.b64 [%0], %1;" :: "r"(a), "r"(cnt) : "memory");
}
__device__ __forceinline__ void mbar_expect(uint32_t a, uint32_t tx) {
    asm volatile("mbarrier.arrive.expect_tx.shared.b64 _, [%0], %1;" :: "r"(a), "r"(tx) : "memory");
}
__device__ __forceinline__ void mbar_wait(uint32_t a, uint32_t parity) {
    asm volatile(
        "{\n\t.reg .pred P;\n\t"
        "WL_%=:\n\t"
        "mbarrier.try_wait.parity.acquire.cta.shared::cta.b64 P, [%0], %1, 0x989680;\n\t"
        "@P bra WD_%=;\n\t"
        "bra WL_%=;\n\t"
        "WD_%=:\n\t}"
        :: "r"(a), "r"(parity) : "memory");
}
__device__ __forceinline__ void bulk_g2s(uint32_t dst, const void* src, uint32_t bytes,
                                         uint32_t mbar) {
    asm volatile(
        "cp.async.bulk.shared::cta.global.mbarrier::complete_tx::bytes [%0], [%1], %2, [%3];"
        :: "r"(dst), "l"(src), "r"(bytes), "r"(mbar) : "memory");
}
__device__ __forceinline__ void ldm_x4(uint32_t& r0, uint32_t& r1, uint32_t& r2,
                                       uint32_t& r3, uint32_t addr) {
    asm volatile("ldmatrix.sync.aligned.m8n8.x4.shared.b16 {%0,%1,%2,%3}, [%4];"
                 : "=r"(r0), "=r"(r1), "=r"(r2), "=r"(r3) : "r"(addr));
}
__device__ __forceinline__ void mma_bf16(float* c, uint32_t a0, uint32_t a1,
                                         uint32_t a2, uint32_t a3,
                                         uint32_t b0, uint32_t b1) {
    asm volatile(
        "mma.sync.aligned.m16n8k16.row.col.f32.bf16.bf16.f32 "
        "{%0,%1,%2,%3}, {%4,%5,%6,%7}, {%8,%9}, {%0,%1,%2,%3};"
        : "+f"(c[0]), "+f"(c[1]), "+f"(c[2]), "+f"(c[3])
        : "r"(a0), "r"(a1), "r"(a2), "r"(a3), "r"(b0), "r"(b1));
}
__device__ __forceinline__ ull pack2(float x, float y) {
    ull r; asm("mov.b64 %0, {%1,%2};" : "=l"(r) : "f"(x), "f"(y)); return r;
}
__device__ __forceinline__ void unpack2(ull v, float& x, float& y) {
    asm("mov.b64 {%0,%1}, %2;" : "=f"(x), "=f"(y) : "l"(v));
}
__device__ __forceinline__ void ffma2(ull& d, ull a, ull b) {
    asm("fma.rn.f32x2 %0, %1, %2, %0;" : "+l"(d) : "l"(a), "l"(b));
}
__device__ __forceinline__ float sigm_(float x) {
    return __fdividef(1.0f, 1.0f + __expf(-x));
}
__device__ __forceinline__ float tanh_(float x) {
    return 1.0f - __fdividef(2.0f, __expf(2.0f * x) + 1.0f);
}

// ---------------- init ------------------------------------------------------------
__global__ void init_state(float* __restrict__ out) {
    int i = blockIdx.x * blockDim.x + threadIdx.x;  // 65536 threads
    ((uint32_t*)g_h_img[0])[i] = 0u;   // zero pp=0 h image (256 KB)
    out[i] = 0.0f;
    if (i == 0) g_bar_cnt = 0u;
}

// ---------------- W_hh -> pre-swizzled per-CTA chunk images -------------------------
__global__ __launch_bounds__(256) void w_prep(const float* __restrict__ Whh) {
    int bid = blockIdx.x;            // 4096 = 128 jb x 32 nl
    int jb = bid >> 5;
    int nl = bid & 31;
    int grow = (nl >> 3) * Hdim + jb * 8 + (nl & 7);
    const float* src = Whh + (size_t)grow * Hdim;
#pragma unroll
    for (int q = 0; q < 4; q++) {
        int k = q * 256 + threadIdx.x;
        float w = src[k];
        __nv_bfloat16 hi = __float2bfloat16(w);
        __nv_bfloat16 lo = __float2bfloat16(w - __bfloat162float(hi));
        int kc = k >> 7;
        int kk = k & 127;
        int seg = kk >> 3;
        uint32_t off = (uint32_t)(nl * 256 + ((seg ^ (nl & 7)) << 4) + (kk & 7) * 2);
        *(__nv_bfloat16*)(&g_w_img[jb][0][kc][off]) = hi;
        *(__nv_bfloat16*)(&g_w_img[jb][1][kc][off]) = lo;
    }
}

// ---------------- GEMM1 (fp32x2 SIMT, proven) ---------------------------------------
__global__ __launch_bounds__(256) void gates_x_gemm(
    const float* __restrict__ seq, const float* __restrict__ Wih,
    const float* __restrict__ bih, const float* __restrict__ bhh) {
    __shared__ float As[8][132];
    __shared__ float Bs[8][132];

    const int tid = threadIdx.x;
    const int tx = tid & 15;
    const int ty = tid >> 4;
    const int m0 = blockIdx.y * 128;
    const int n0 = blockIdx.x * 128;

    const int lr = tid >> 1;
    const int lk = (tid & 1) * 4;
    const float* aptr = seq + (size_t)(m0 + lr) * Idim + lk;
    const float* bptr = Wih + (size_t)(n0 + lr) * Idim + lk;

    ull acc[8][4];
#pragma unroll
    for (int i = 0; i < 8; i++)
#pragma unroll
        for (int j = 0; j < 4; j++) acc[i][j] = 0ull;

    for (int k0 = 0; k0 < Idim; k0 += 8) {
        float4 av = *(const float4*)(aptr + k0);
        float4 bv = *(const float4*)(bptr + k0);
        As[lk + 0][lr] = av.x; As[lk + 1][lr] = av.y;
        As[lk + 2][lr] = av.z; As[lk + 3][lr] = av.w;
        Bs[lk + 0][lr] = bv.x; Bs[lk + 1][lr] = bv.y;
        Bs[lk + 2][lr] = bv.z; Bs[lk + 3][lr] = bv.w;
        __syncthreads();
#pragma unroll
        for (int k = 0; k < 8; k++) {
            float4 a0 = *(const float4*)&As[k][ty * 8];
            float4 a1 = *(const float4*)&As[k][ty * 8 + 4];
            ull pb0 = *(const ull*)&Bs[k][tx * 8 + 0];
            ull pb1 = *(const ull*)&Bs[k][tx * 8 + 2];
            ull pb2 = *(const ull*)&Bs[k][tx * 8 + 4];
            ull pb3 = *(const ull*)&Bs[k][tx * 8 + 6];
            float am[8] = {a0.x, a0.y, a0.z, a0.w, a1.x, a1.y, a1.z, a1.w};
#pragma unroll
            for (int i = 0; i < 8; i++) {
                ull pa = pack2(am[i], am[i]);
                ffma2(acc[i][0], pa, pb0);
                ffma2(acc[i][1], pa, pb1);
                ffma2(acc[i][2], pa, pb2);
                ffma2(acc[i][3], pa, pb3);
            }
        }
        __syncthreads();
    }

#pragma unroll
    for (int i = 0; i < 8; i++) {
        int m = m0 + ty * 8 + i;
        int b = m >> 9;        // T = 512
        int t = m & 511;
        float* orow = g_gates_x + (size_t)(t * Bdim + b) * Gdim;
#pragma unroll
        for (int j = 0; j < 4; j++) {
            int n = n0 + tx * 8 + j * 2;
            float x, y; unpack2(acc[i][j], x, y);
            orow[n]     = x + bih[n]     + bhh[n];
            orow[n + 1] = y + bih[n + 1] + bhh[n + 1];
        }
    }
}

// ---------------- persistent HMMA recurrence (bulk DMA, W resident) -----------------
// 128 CTAs (1/SM) x 256 thr (8 warps). W_hh slice bf16 hi/lo (128 KB) bulk-copied to
// smem ONCE. Per step: h streamed via 16 bulk DMAs into a 2-stage 32KB ring. c-state
// and lens in registers for all 512 steps. Spin grid barrier per step.
// Warp w: mt=w&3 (batches mt*16..), nh=w>>2 (gate cols nh*16..). Per k16: 2 A-LDSM.x4
// + 2 B-LDSM.x4, 6 MMAs (3 split terms).
#define OFF_W 0                          // [plane][kc][8192] = 131072 B
#define OFF_H 131072                     // 2 stages x (Ahi 16384 | Alo 16384)
#define OFF_PRE (OFF_H + 2 * 32768)      // 196608
#define OFF_MBAR (OFF_PRE + 64 * 36 * 4) // 205824 (mb_h0, mb_h1, mb_w)
#define SMEM_BYTES (OFF_MBAR + 64)       // 205888

__global__ __launch_bounds__(256, 1) void lstm_persist(
    const int* __restrict__ lens, float* __restrict__ out) {
    extern __shared__ unsigned char smem[];
    const uint32_t sb = smem_u32(smem);
    float* pre = (float*)(smem + OFF_PRE);        // [64][36]
    const uint32_t mb_h = sb + OFF_MBAR;          // 2 stage mbars, 8B apart
    const uint32_t mb_w = sb + OFF_MBAR + 16;

    const int tid = threadIdx.x;
    const int lane = tid & 31;
    const int w = tid >> 5;
    const int mt = w & 3;
    const int nh = w >> 2;
    const int jb = blockIdx.x;
    const int j0 = jb * 8;

    if (tid == 0) {
        mbar_init(mb_h, 1);
        mbar_init(mb_h + 8, 1);
        mbar_init(mb_w, 1);
    }
    __syncthreads();

    // ---- one-time: W slice (both planes) -> smem via 2 bulk copies
    if (tid == 0) {
        mbar_expect(mb_w, 131072);
        bulk_g2s(sb + OFF_W,         &g_w_img[jb][0][0][0], 65536, mb_w);
        bulk_g2s(sb + OFF_W + 65536, &g_w_img[jb][1][0][0], 65536, mb_w);
    }
    mbar_wait(mb_w, 0);

    // ---- per-lane fragment addressing (proven round 10)
    const int rowa = mt * 16 + (lane & 7) + ((lane >> 3) & 1) * 8;   // A row (batch)
    const int selA = (lane >> 4) & 1;
    const int xa = rowa & 7;
    const uint32_t a_base = (uint32_t)(rowa * 256);
    const int rowb = nh * 16 + (lane & 7) + ((lane >> 4) & 1) * 8;   // B row (gate col)
    const int selB = (lane >> 3) & 1;
    const int xb = rowb & 7;
    const uint32_t b_base = (uint32_t)(rowb * 256);

    // ---- persistent per-thread state (threads 0-63: b = tid)
    float cst[8];
#pragma unroll
    for (int q = 0; q < 8; q++) cst[q] = 0.0f;
    const int lb = (tid < 64) ? lens[tid] : 0;

    // epilogue h-image addressing
    const int jc = j0 >> 7;
    const int sg = (j0 & 127) >> 3;

    for (int t = 0; t < Tdim; t++) {
        const int pp = t & 1;

        // bulk issuer: chunk kc of this step -> stage (t*8+kc)&1
        auto issue_chunk = [&](int kc) {
            int n = t * 8 + kc;
            int s = n & 1;
            uint32_t dst = sb + OFF_H + s * 32768;
            uint32_t mb = mb_h + s * 8;
            mbar_expect(mb, 32768);
            bulk_g2s(dst,         &g_h_img[pp][0][kc][0], 16384, mb);
            bulk_g2s(dst + 16384, &g_h_img[pp][1][kc][0], 16384, mb);
        };

        if (tid == 0) { issue_chunk(0); issue_chunk(1); }

        // gates_x prefetch (threads 0-63, b = tid)
        float gx[32];
        if (tid < 64) {
            const float* gxb = g_gates_x + ((size_t)t * Bdim + tid) * Gdim + j0;
#pragma unroll
            for (int g = 0; g < 4; g++) {
                float4 v0 = *(const float4*)(gxb + g * Hdim);
                float4 v1 = *(const float4*)(gxb + g * Hdim + 4);
                gx[g * 8 + 0] = v0.x; gx[g * 8 + 1] = v0.y;
                gx[g * 8 + 2] = v0.z; gx[g * 8 + 3] = v0.w;
                gx[g * 8 + 4] = v1.x; gx[g * 8 + 5] = v1.y;
                gx[g * 8 + 6] = v1.z; gx[g * 8 + 7] = v1.w;
            }
        }

        float C0[2][4], C1[2][4], C2[2][4];
#pragma unroll
        for (int nt = 0; nt < 2; nt++)
#pragma unroll
            for (int k = 0; k < 4; k++) { C0[nt][k] = 0.f; C1[nt][k] = 0.f; C2[nt][k] = 0.f; }

        for (int kc = 0; kc < 8; kc++) {
            int n = t * 8 + kc;
            mbar_wait(mb_h + (n & 1) * 8, (n >> 1) & 1);

            uint32_t abase = sb + OFF_H + (n & 1) * 32768 + a_base;
            uint32_t bbase = sb + OFF_W + kc * 8192 + b_base;
#pragma unroll
            for (int ks = 0; ks < 8; ks++) {
                uint32_t aoff = abase + (uint32_t)((((2 * ks + selA) ^ xa)) << 4);
                uint32_t boff = bbase + (uint32_t)((((2 * ks + selB) ^ xb)) << 4);
                uint32_t ah0, ah1, ah2, ah3, al0, al1, al2, al3;
                ldm_x4(ah0, ah1, ah2, ah3, aoff);
                ldm_x4(al0, al1, al2, al3, aoff + 16384);
                uint32_t p0, p1, p2, p3;          // B hi
                ldm_x4(p0, p1, p2, p3, boff);
                uint32_t s0, s1, s2, s3;          // B lo
                ldm_x4(s0, s1, s2, s3, boff + 65536);

                mma_bf16(C0[0], ah0, ah1, ah2, ah3, p0, p1);
                mma_bf16(C0[1], ah0, ah1, ah2, ah3, p2, p3);
                mma_bf16(C1[0], ah0, ah1, ah2, ah3, s0, s1);
                mma_bf16(C1[1], ah0, ah1, ah2, ah3, s2, s3);
                mma_bf16(C2[0], al0, al1, al2, al3, p0, p1);
                mma_bf16(C2[1], al0, al1, al2, al3, p2, p3);
            }
            __syncthreads();                      // reads of stage n&1 retired
            if (tid == 0 && kc + 2 < 8) issue_chunk(kc + 2);
        }

        // merge split terms -> pre[64][36]
        {
            int g = lane >> 2, t2 = (lane & 3) * 2;
            int m = mt * 16 + g;
#pragma unroll
            for (int nt = 0; nt < 2; nt++) {
                float s0 = C0[nt][0] + C1[nt][0] + C2[nt][0];
                float s1 = C0[nt][1] + C1[nt][1] + C2[nt][1];
                float s2 = C0[nt][2] + C1[nt][2] + C2[nt][2];
                float s3 = C0[nt][3] + C1[nt][3] + C2[nt][3];
                int nn = nh * 16 + nt * 8 + t2;
                *(float2*)&pre[m * 36 + nn]       = make_float2(s0, s1);
                *(float2*)&pre[(m + 8) * 36 + nn] = make_float2(s2, s3);
            }
        }
        __syncthreads();

        // pointwise LSTM cell (threads 0-63, b = tid)
        if (tid < 64) {
            int b = tid;
            float hn[8];
            unsigned short hu[8], lu[8];
#pragma unroll
            for (int jj = 0; jj < 8; jj++) {
                float xi = pre[b * 36 + jj]      + gx[jj];
                float xf = pre[b * 36 + 8 + jj]  + gx[8 + jj];
                float xg = pre[b * 36 + 16 + jj] + gx[16 + jj];
                float xo = pre[b * 36 + 24 + jj] + gx[24 + jj];
                float i_ = sigm_(xi), f_ = sigm_(xf), g_ = tanh_(xg), o_ = sigm_(xo);
                float cn = f_ * cst[jj] + i_ * g_;
                cst[jj] = cn;
                float h = o_ * tanh_(cn);
                hn[jj] = h;
                __nv_bfloat16 hh = __float2bfloat16(h);
                __nv_bfloat16 hl = __float2bfloat16(h - __bfloat162float(hh));
                hu[jj] = __bfloat16_as_ushort(hh);
                lu[jj] = __bfloat16_as_ushort(hl);
            }
            uint4 vh, vl;
            vh.x = (uint32_t)hu[0] | ((uint32_t)hu[1] << 16);
            vh.y = (uint32_t)hu[2] | ((uint32_t)hu[3] << 16);
            vh.z = (uint32_t)hu[4] | ((uint32_t)hu[5] << 16);
            vh.w = (uint32_t)hu[6] | ((uint32_t)hu[7] << 16);
            vl.x = (uint32_t)lu[0] | ((uint32_t)lu[1] << 16);
            vl.y = (uint32_t)lu[2] | ((uint32_t)lu[3] << 16);
            vl.z = (uint32_t)lu[4] | ((uint32_t)lu[5] << 16);
            vl.w = (uint32_t)lu[6] | ((uint32_t)lu[7] << 16);

            int pp1 = pp ^ 1;
            uint32_t hoff = (uint32_t)(b * 256 + ((sg ^ (b & 7)) << 4));
            *(uint4*)(&g_h_img[pp1][0][jc][hoff]) = vh;
            *(uint4*)(&g_h_img[pp1][1][jc][hoff]) = vl;

            if (lb > t) {
                float* ob = out + (size_t)b * Hdim + j0;
                *(float4*)(ob)     = make_float4(hn[0], hn[1], hn[2], hn[3]);
                *(float4*)(ob + 4) = make_float4(hn[4], hn[5], hn[6], hn[7]);
            }
            // make generic-proxy h stores visible to next step's async-proxy bulk reads
            asm volatile("fence.proxy.async;" ::: "memory");
        }

        // grid barrier (release h writes, acquire peers')
        __syncthreads();
        if (tid == 0) {
            __threadfence();
            atomicAdd(&g_bar_cnt, 1u);
            unsigned target = (unsigned)(t + 1) * (unsigned)NCTA;
            while (*(volatile unsigned*)&g_bar_cnt < target) { }
            __threadfence();
        }
        __syncthreads();
    }
}

// ---------------- launch ------------------------------------------------------------
extern "C" void kernel_launch(void* const* d_in, const int* in_sizes, int n_in,
                              void* d_out, int out_size) {
    const float* seq   = (const float*)d_in[0];
    const int*   lensp = (const int*)d_in[1];
    const float* Wih   = (const float*)d_in[2];
    const float* Whh   = (const float*)d_in[3];
    const float* bih   = (const float*)d_in[4];
    const float* bhh   = (const float*)d_in[5];
    float* out = (float*)d_out;

    cudaFuncSetAttribute(lstm_persist,
                         cudaFuncAttributeMaxDynamicSharedMemorySize, SMEM_BYTES);

    init_state<<<256, 256>>>(out);
    w_prep<<<4096, 256>>>(Whh);

    dim3 g1(Gdim / 128, (Bdim * Tdim) / 128);
    gates_x_gemm<<<g1, 256>>>(seq, Wih, bih, bhh);

    lstm_persist<<<NCTA, 256, SMEM_BYTES>>>(lensp, out);
}